// round 1
// baseline (speedup 1.0000x reference)
#include <cuda_runtime.h>
#include <math.h>

// ---------------- problem constants ----------------
#define NLEV   16
#define TBL    524288u          // T = 2^19 entries per level
#define TMASK  (TBL - 1u)
#define HP1    2654435761u
#define HP2    805459861u

typedef unsigned long long ull;

// MLP weights live in constant memory: uniform (warp-wide identical) accesses
// compile to LDCU (uniform port, rt=1) instead of LDS/LDG, leaving the LSU
// free for the table gathers.
__constant__ __align__(16) float cW1[32 * 64];
__constant__ __align__(16) float cW2[64 * 16];

struct LevelParams {
    float    resf[NLEV];   // (float)res[l]
    unsigned s[NLEV];      // res[l] + 1  (dense stride)
    unsigned dense[NLEV];  // (res+1)^3 <= T ?
};

// ---------------- packed f32x2 helpers (Blackwell FFMA2) ----------------
__device__ __forceinline__ ull pack2(float v) {
    ull r;
    unsigned u = __float_as_uint(v);
    asm("mov.b64 %0, {%1,%1};" : "=l"(r) : "r"(u));
    return r;
}
__device__ __forceinline__ ull fma2(ull a, ull b, ull c) {
    ull d;
    asm("fma.rn.f32x2 %0, %1, %2, %3;" : "=l"(d) : "l"(a), "l"(b), "l"(c));
    return d;
}
__device__ __forceinline__ float2 unpack2(ull v) {
    unsigned lo, hi;
    asm("mov.b64 {%0,%1}, %2;" : "=r"(lo), "=r"(hi) : "l"(v));
    return make_float2(__uint_as_float(lo), __uint_as_float(hi));
}

// ---------------- fused kernel: hashgrid encode + MLP ----------------
__global__ void __launch_bounds__(256)
hashgrid_mlp_kernel(const float* __restrict__ xyzs,
                    const float* __restrict__ tables,
                    float* __restrict__ out,
                    int N, LevelParams lp)
{
    int pid = blockIdx.x * blockDim.x + threadIdx.x;
    if (pid >= N) return;

    float x = xyzs[3 * pid + 0];
    float y = xyzs[3 * pid + 1];
    float z = xyzs[3 * pid + 2];

    // x01 = clip((x + 1) / 2, 0, 1)
    float x01 = fminf(fmaxf((x + 1.0f) * 0.5f, 0.0f), 1.0f);
    float y01 = fminf(fmaxf((y + 1.0f) * 0.5f, 0.0f), 1.0f);
    float z01 = fminf(fmaxf((z + 1.0f) * 0.5f, 0.0f), 1.0f);

    float enc[32];

#pragma unroll
    for (int l = 0; l < NLEV; l++) {
        const float2* __restrict__ tab =
            reinterpret_cast<const float2*>(tables) + (size_t)l * TBL;

        float rf = lp.resf[l];
        float px = x01 * rf, py = y01 * rf, pz = z01 * rf;
        float fpx = floorf(px), fpy = floorf(py), fpz = floorf(pz);
        float fx = px - fpx, fy = py - fpy, fz = pz - fpz;
        unsigned ix = (unsigned)fpx, iy = (unsigned)fpy, iz = (unsigned)fpz;
        float wx0 = 1.0f - fx, wy0 = 1.0f - fy, wz0 = 1.0f - fz;

        // 8 corner indices + weights; x-corner pair per (y,z) combo.
        unsigned idx0a[4], idx1a[4];
        float    wyzs[4];
        if (lp.dense[l]) {
            unsigned s = lp.s[l];
#pragma unroll
            for (int k = 0; k < 2; k++) {
#pragma unroll
                for (int j = 0; j < 2; j++) {
                    unsigned a = s * ((iy + (unsigned)j) + s * (iz + (unsigned)k));
                    int c = k * 2 + j;
                    idx0a[c] = ix + a;
                    idx1a[c] = ix + 1u + a;
                    wyzs[c]  = (j ? fy : wy0) * (k ? fz : wz0);
                }
            }
        } else {
            unsigned hy0 = iy * HP1;
            unsigned hz0 = iz * HP2;
#pragma unroll
            for (int k = 0; k < 2; k++) {
#pragma unroll
                for (int j = 0; j < 2; j++) {
                    unsigned a = (hy0 + (j ? HP1 : 0u)) ^ (hz0 + (k ? HP2 : 0u));
                    int c = k * 2 + j;
                    idx0a[c] = (ix ^ a) & TMASK;
                    idx1a[c] = ((ix + 1u) ^ a) & TMASK;
                    wyzs[c]  = (j ? fy : wy0) * (k ? fz : wz0);
                }
            }
        }

        // Issue all 8 gathers (independent -> MLP-grade ILP), then reduce.
        float2 v0[4], v1[4];
#pragma unroll
        for (int c = 0; c < 4; c++) {
            v0[c] = __ldg(&tab[idx0a[c]]);
            v1[c] = __ldg(&tab[idx1a[c]]);
        }
        float e0 = 0.0f, e1 = 0.0f;
#pragma unroll
        for (int c = 0; c < 4; c++) {
            float w0 = wx0 * wyzs[c];
            float w1 = fx  * wyzs[c];
            e0 = fmaf(w0, v0[c].x, e0);
            e1 = fmaf(w0, v0[c].y, e1);
            e0 = fmaf(w1, v1[c].x, e0);
            e1 = fmaf(w1, v1[c].y, e1);
        }
        enc[2 * l]     = e0;
        enc[2 * l + 1] = e1;
    }

    // ---------------- MLP layer 1: h = relu(enc @ W1), W1[32][64] ----------------
    ull hp[32];
#pragma unroll
    for (int j = 0; j < 32; j++) hp[j] = 0ull;

#pragma unroll
    for (int i = 0; i < 32; i++) {
        ull ee = pack2(enc[i]);
        const ulonglong2* wrow =
            reinterpret_cast<const ulonglong2*>(cW1 + i * 64);
#pragma unroll
        for (int j = 0; j < 16; j++) {
            ulonglong2 w = wrow[j];            // 4 weights (2 packed pairs)
            hp[2 * j]     = fma2(ee, w.x, hp[2 * j]);
            hp[2 * j + 1] = fma2(ee, w.y, hp[2 * j + 1]);
        }
    }

    float h[64];
#pragma unroll
    for (int j = 0; j < 32; j++) {
        float2 p = unpack2(hp[j]);
        h[2 * j]     = fmaxf(p.x, 0.0f);
        h[2 * j + 1] = fmaxf(p.y, 0.0f);
    }

    // ---------------- MLP layer 2: out = h @ W2, W2[64][16] ----------------
    ull op[8];
#pragma unroll
    for (int j = 0; j < 8; j++) op[j] = 0ull;

#pragma unroll
    for (int i = 0; i < 64; i++) {
        ull ee = pack2(h[i]);
        const ulonglong2* wrow =
            reinterpret_cast<const ulonglong2*>(cW2 + i * 16);
#pragma unroll
        for (int j = 0; j < 4; j++) {
            ulonglong2 w = wrow[j];
            op[2 * j]     = fma2(ee, w.x, op[2 * j]);
            op[2 * j + 1] = fma2(ee, w.y, op[2 * j + 1]);
        }
    }

    float o[16];
#pragma unroll
    for (int j = 0; j < 8; j++) {
        float2 p = unpack2(op[j]);
        o[2 * j]     = p.x;
        o[2 * j + 1] = p.y;
    }

    // sigmas first (N floats), then geo_features (N x 15 row-major)
    out[pid] = expf(o[0]);
    float* g = out + (size_t)N + (size_t)pid * 15;
#pragma unroll
    for (int k = 0; k < 15; k++) g[k] = o[k + 1];
}

// ---------------- host launch ----------------
static LevelParams make_level_params()
{
    LevelParams lp;
    // Replicate numpy float64 math exactly:
    // PLS = exp(log(2048/16)/15); RES[l] = ceil(16 * PLS**l)
    double pls = exp(log(2048.0 / 16.0) / (double)(NLEV - 1));
    for (int l = 0; l < NLEV; l++) {
        int r = (int)ceil(16.0 * pow(pls, (double)l));
        lp.resf[l]  = (float)r;
        lp.s[l]     = (unsigned)(r + 1);
        long long s = (long long)(r + 1);
        lp.dense[l] = (s * s * s <= (long long)TBL) ? 1u : 0u;
    }
    return lp;
}

extern "C" void kernel_launch(void* const* d_in, const int* in_sizes, int n_in,
                              void* d_out, int out_size)
{
    (void)n_in; (void)out_size;
    const float* xyzs   = (const float*)d_in[0];
    const float* tables = (const float*)d_in[1];
    int N = in_sizes[0] / 3;

    // Weights -> constant memory (D2D async copy: graph-capturable memcpy node)
    cudaMemcpyToSymbolAsync(cW1, d_in[2], 32 * 64 * sizeof(float), 0,
                            cudaMemcpyDeviceToDevice, 0);
    cudaMemcpyToSymbolAsync(cW2, d_in[3], 64 * 16 * sizeof(float), 0,
                            cudaMemcpyDeviceToDevice, 0);

    LevelParams lp = make_level_params();

    int block = 256;
    int grid  = (N + block - 1) / block;
    hashgrid_mlp_kernel<<<grid, block>>>(xyzs, tables, (float*)d_out, N, lp);
}